// round 16
// baseline (speedup 1.0000x reference)
#include <cuda_runtime.h>
#include <cuda_fp16.h>
#include <cstdint>
#include <math.h>

// ---------------------------------------------------------------- constants
#define BB   2
#define SS   2048
#define HIDD 2048
#define NH   32
#define NKV  8
#define DH   64
#define MROWS (BB*SS)        // 4096
#define KVDIM (NKV*DH)       // 512
#define KDIM  2048
#define QKVDIM (HIDD + 2*KVDIM)   // 3072

// ---------------------------------------------------------------- scratch
__device__ float  g_qkv [(size_t)MROWS * QKVDIM];   // 48 MB
__device__ __half g_hs_h[(size_t)MROWS * KDIM];     // 16 MB fp16(hs)
__device__ __half g_w_h [(size_t)QKVDIM * KDIM];    // 12 MB fp16(W) merged
__device__ __half g_wo_h[(size_t)HIDD  * KDIM];     //  8 MB
__device__ __half g_at_h[(size_t)MROWS * KDIM];     // 16 MB fp16(attn out)
__device__ __half g_kv16[(size_t)MROWS * 1024];     //  8 MB fp16 K|V (roped)

// ---------------------------------------------------------------- helpers
__device__ __forceinline__ uint32_t smem_u32(const void* p) {
    uint32_t a;
    asm("{ .reg .u64 t; cvta.to.shared.u64 t, %1; cvt.u32.u64 %0, t; }" : "=r"(a) : "l"(p));
    return a;
}
__device__ __forceinline__ void cpa16(uint32_t s, const void* g) {
    asm volatile("cp.async.cg.shared.global [%0], [%1], 16;" :: "r"(s), "l"(g));
}
__device__ __forceinline__ void cpa_commit() {
    asm volatile("cp.async.commit_group;" ::: "memory");
}
template<int N> __device__ __forceinline__ void cpa_wait() {
    asm volatile("cp.async.wait_group %0;" :: "n"(N) : "memory");
}
__device__ __forceinline__ void ldsm_x4(uint32_t& r0, uint32_t& r1, uint32_t& r2, uint32_t& r3,
                                        uint32_t addr) {
    asm volatile("ldmatrix.sync.aligned.m8n8.x4.shared.b16 {%0,%1,%2,%3}, [%4];"
                 : "=r"(r0), "=r"(r1), "=r"(r2), "=r"(r3) : "r"(addr));
}
__device__ __forceinline__ void ldsm_x4t(uint32_t& r0, uint32_t& r1, uint32_t& r2, uint32_t& r3,
                                         uint32_t addr) {
    asm volatile("ldmatrix.sync.aligned.m8n8.x4.trans.shared.b16 {%0,%1,%2,%3}, [%4];"
                 : "=r"(r0), "=r"(r1), "=r"(r2), "=r"(r3) : "r"(addr));
}
__device__ __forceinline__ void mma_f16(float& c0, float& c1, float& c2, float& c3,
                                        uint32_t a0, uint32_t a1, uint32_t a2, uint32_t a3,
                                        uint32_t b0, uint32_t b1) {
    asm volatile(
        "mma.sync.aligned.m16n8k16.row.col.f32.f16.f16.f32 "
        "{%0,%1,%2,%3}, {%4,%5,%6,%7}, {%8,%9}, {%0,%1,%2,%3};"
        : "+f"(c0), "+f"(c1), "+f"(c2), "+f"(c3)
        : "r"(a0), "r"(a1), "r"(a2), "r"(a3), "r"(b0), "r"(b1));
}

// ---------------------------------------------------------------- converts
__global__ void conv_kernel(const float* __restrict__ s, __half* __restrict__ d, int n) {
    int idx = blockIdx.x * blockDim.x + threadIdx.x;
    if (idx < n) d[idx] = __float2half(s[idx]);
}
__global__ void conv_w_kernel(const float* __restrict__ Wq, const float* __restrict__ Wk,
                              const float* __restrict__ Wv, const float* __restrict__ Wo,
                              __half* __restrict__ wh, __half* __restrict__ woh) {
    int idx = blockIdx.x * blockDim.x + threadIdx.x;
    if (idx >= (QKVDIM + HIDD) * KDIM) return;
    int r = idx >> 11;
    int k = idx & (KDIM - 1);
    float x;
    if (r < HIDD)                 x = Wq[(size_t)r * KDIM + k];
    else if (r < HIDD + KVDIM)    x = Wk[(size_t)(r - HIDD) * KDIM + k];
    else if (r < QKVDIM)          x = Wv[(size_t)(r - HIDD - KVDIM) * KDIM + k];
    else                          x = Wo[(size_t)(r - QKVDIM) * KDIM + k];
    if (r < QKVDIM) wh[idx] = __float2half(x);
    else            woh[(size_t)(r - QKVDIM) * KDIM + k] = __float2half(x);
}
// Fused: rope K (fp32 read from qkv) -> fp16 kv buffer; convert V -> fp16.
__global__ void ropeKV_kernel(const float* __restrict__ qkv,
                              const float* __restrict__ cs, const float* __restrict__ sn,
                              __half* __restrict__ kv) {
    int idx = blockIdx.x * blockDim.x + threadIdx.x;
    const int KP = MROWS * 256;
    if (idx < KP) {
        int d = idx & 31;
        int h = (idx >> 5) & (NKV - 1);
        int r = idx >> 8;
        float c = cs[r * DH + d], s = sn[r * DH + d];
        const float* p = qkv + (size_t)r * QKVDIM + HIDD + h * DH + d;
        float x1 = p[0], x2 = p[32];
        kv[(size_t)r * 1024 + h * DH + d]      = __float2half(x1 * c - x2 * s);
        kv[(size_t)r * 1024 + h * DH + d + 32] = __float2half(x2 * c + x1 * s);
    } else {
        int e = idx - KP;
        int r = e >> 8;
        int c2 = (e & 255) * 2;
        const float* p = qkv + (size_t)r * QKVDIM + HIDD + 512 + c2;
        kv[(size_t)r * 1024 + 512 + c2]     = __float2half(p[0]);
        kv[(size_t)r * 1024 + 512 + c2 + 1] = __float2half(p[1]);
    }
}

// ---------------------------------------------------------------- fp16 HMMA GEMM, BK=64
// C[M,N] = A[M,KDIM] * B[N,KDIM]^T. 128x128 tile, 8 warps, 3-stage cp.async, occ 2.
#define BKG   64
#define NKIT  (KDIM / BKG)       // 32
#define SROWB 144                // 128B data + 16B pad per row
#define TILE_B (128 * SROWB)     // 18432
#define STAGE_B (2 * TILE_B)     // 36864 (A + B)
#define GSMEM  (3 * STAGE_B)     // 110592

__global__ __launch_bounds__(256, 2) void gemm_f16(
    const __half* __restrict__ A, const __half* __restrict__ B,
    float* __restrict__ C, int N)
{
    extern __shared__ __align__(128) char smem[];
    const uint32_t sb = smem_u32(smem);
    const int tid  = threadIdx.x;
    const int lane = tid & 31;
    const int wid  = tid >> 5;
    const int wm   = wid & 3;
    const int wn   = wid >> 2;
    const int bm = blockIdx.y * 128, bn = blockIdx.x * 128;

    // loader: threads 0-127 -> A rows, 128-255 -> B rows; one full 128B row each
    const int lr = tid & 127;
    const bool isB = tid >= 128;
    const __half* gsrc = isB ? B + (size_t)(bn + lr) * KDIM
                             : A + (size_t)(bm + lr) * KDIM;
    const uint32_t sdst = sb + (isB ? TILE_B : 0) + lr * SROWB;

    float acc[2][8][4];
#pragma unroll
    for (int i = 0; i < 2; i++)
#pragma unroll
        for (int j = 0; j < 8; j++)
#pragma unroll
            for (int r = 0; r < 4; r++) acc[i][j][r] = 0.f;

    const int a_row = wm * 32 + (lane & 15);
    const int a_kb  = (lane >> 4) * 16;
    const int b_row = wn * 64 + ((lane >> 4) << 3) + (lane & 7);
    const int b_kb  = ((lane >> 3) & 1) * 16;

    // prologue: stages 0,1
#pragma unroll
    for (int s = 0; s < 2; s++) {
        const uint32_t sd = sdst + s * STAGE_B;
        const int k0 = s * BKG;
#pragma unroll
        for (int c = 0; c < 8; c++) cpa16(sd + c * 16, gsrc + k0 + c * 8);
        cpa_commit();
    }

    for (int kt = 0; kt < NKIT; kt++) {
        cpa_wait<1>();
        __syncthreads();

        if (kt + 2 < NKIT) {
            const uint32_t sd = sdst + ((kt + 2) % 3) * STAGE_B;
            const int k0 = (kt + 2) * BKG;
#pragma unroll
            for (int c = 0; c < 8; c++) cpa16(sd + c * 16, gsrc + k0 + c * 8);
        }
        cpa_commit();

        const uint32_t sAs = sb + (kt % 3) * STAGE_B;
        const uint32_t sBs = sAs + TILE_B;

#pragma unroll
        for (int kh = 0; kh < 4; kh++) {
            const int kbyte = kh * 32;
            uint32_t a[2][4];
#pragma unroll
            for (int mt = 0; mt < 2; mt++)
                ldsm_x4(a[mt][0], a[mt][1], a[mt][2], a[mt][3],
                        sAs + (a_row + mt * 16) * SROWB + kbyte + a_kb);
            uint32_t b[4][4];
#pragma unroll
            for (int nt = 0; nt < 4; nt++)
                ldsm_x4(b[nt][0], b[nt][1], b[nt][2], b[nt][3],
                        sBs + (b_row + nt * 16) * SROWB + kbyte + b_kb);
#pragma unroll
            for (int mt = 0; mt < 2; mt++)
#pragma unroll
                for (int j = 0; j < 8; j++)
                    mma_f16(acc[mt][j][0], acc[mt][j][1], acc[mt][j][2], acc[mt][j][3],
                            a[mt][0], a[mt][1], a[mt][2], a[mt][3],
                            b[j >> 1][(j & 1) * 2], b[j >> 1][(j & 1) * 2 + 1]);
        }
        __syncthreads();
    }

#pragma unroll
    for (int mt = 0; mt < 2; mt++) {
        int m0 = bm + wm * 32 + mt * 16 + (lane >> 2);
#pragma unroll
        for (int j = 0; j < 8; j++) {
            int n0 = bn + wn * 64 + j * 8 + (lane & 3) * 2;
            float2 v0 = { acc[mt][j][0], acc[mt][j][1] };
            float2 v1 = { acc[mt][j][2], acc[mt][j][3] };
            *(float2*)(C + (size_t)m0 * N + n0)       = v0;
            *(float2*)(C + (size_t)(m0 + 8) * N + n0) = v1;
        }
    }
}

// ---------------------------------------------------------------- HMMA flash attention (R15)
#define QT 128
#define KT 64
#define PADH 72                       // halves per smem row (144 B)
#define QBUF_B (QT * PADH * 2)        // 18432 B
#define KVBUF_B (KT * PADH * 2)       // 9216 B per buffer
#define ASMEM (QBUF_B + 4 * KVBUF_B)  // 55296 B

__global__ __launch_bounds__(256) void attn_hmma(
    const float* __restrict__ QKV, const __half* __restrict__ KV,
    const float* __restrict__ cs, const float* __restrict__ sn,
    __half* __restrict__ ATH)
{
    extern __shared__ __align__(16) char asmem[];
    const uint32_t sQ = smem_u32(asmem);
    const uint32_t sK = sQ + QBUF_B;
    const uint32_t sV = sK + 2 * KVBUF_B;

    const int tid  = threadIdx.x;
    const int lane = tid & 31;
    const int w    = tid >> 5;
    const int b    = blockIdx.y >> 5;
    const int h    = blockIdx.y & 31;
    const int kvh  = h >> 2;
    const int qt   = gridDim.x - 1 - blockIdx.x;
    const int qbase = qt * QT;
    const int ntiles = 2 * (qt + 1);

    const int lrow = tid >> 2;
    const int lch  = (tid & 3) * 2;
    const __half* kgK = KV + ((size_t)(b * SS) + lrow) * 1024 + kvh * DH;
    const __half* kgV = kgK + 512;
#pragma unroll
    for (int p = 0; p < 2; p++) {
        {
            const size_t off = (size_t)p * KT * 1024;
            uint32_t kd = sK + p * KVBUF_B + lrow * 144;
            uint32_t vd = sV + p * KVBUF_B + lrow * 144;
#pragma unroll
            for (int c = 0; c < 2; c++) {
                int ch = lch + c;
                cpa16(kd + ch * 16, kgK + off + ch * 8);
                cpa16(vd + ch * 16, kgV + off + ch * 8);
            }
        }
        cpa_commit();
    }

    // Q load + RoPE + scale -> fp16 smem
    {
        const int row = tid >> 1;
        const int hs  = tid & 1;
        const int grow = qbase + row;
        const float* qp = QKV + ((size_t)(b * SS + grow)) * QKVDIM + h * DH;
        const float* cp = cs + (size_t)(b * SS + grow) * DH;
        const float* sp = sn + (size_t)(b * SS + grow) * DH;
        __half* qrow = (__half*)(asmem) + row * PADH;
#pragma unroll
        for (int i = 0; i < 8; i++) {
            int d0 = hs * 32 + i * 4;
            float4 xv = *(const float4*)(qp + d0);
            float4 pv = *(const float4*)(qp + (d0 ^ 32));
            float4 cv = *(const float4*)(cp + d0);
            float4 sv = *(const float4*)(sp + d0);
            float o0, o1, o2, o3;
            if (hs == 0) {
                o0 = (xv.x*cv.x - pv.x*sv.x)*0.125f; o1 = (xv.y*cv.y - pv.y*sv.y)*0.125f;
                o2 = (xv.z*cv.z - pv.z*sv.z)*0.125f; o3 = (xv.w*cv.w - pv.w*sv.w)*0.125f;
            } else {
                o0 = (xv.x*cv.x + pv.x*sv.x)*0.125f; o1 = (xv.y*cv.y + pv.y*sv.y)*0.125f;
                o2 = (xv.z*cv.z + pv.z*sv.z)*0.125f; o3 = (xv.w*cv.w + pv.w*sv.w)*0.125f;
            }
            *(__half2*)(qrow + d0)     = __floats2half2_rn(o0, o1);
            *(__half2*)(qrow + d0 + 2) = __floats2half2_rn(o2, o3);
        }
    }
    __syncthreads();

    uint32_t Qf[4][4];
    {
        const int a_row = w * 16 + (lane & 15);
        const int a_kb  = (lane >> 4) * 16;
#pragma unroll
        for (int ks = 0; ks < 4; ks++)
            ldsm_x4(Qf[ks][0], Qf[ks][1], Qf[ks][2], Qf[ks][3],
                    sQ + a_row * 144 + ks * 32 + a_kb);
    }

    float O[8][4];
#pragma unroll
    for (int j = 0; j < 8; j++)
#pragma unroll
        for (int r = 0; r < 4; r++) O[j][r] = 0.f;
    float m0 = -1e30f, m1 = -1e30f, l0 = 0.f, l1 = 0.f;

    const int bKrow = ((lane >> 4) << 3) + (lane & 7);
    const int bKb   = ((lane >> 3) & 1) * 16;
    const int vm = lane >> 3, vr = lane & 7;
    const int grow0 = qbase + w * 16 + (lane >> 2);

    for (int t = 0; t < ntiles; t++) {
        cpa_wait<1>();
        __syncthreads();
        const int buf = t & 1;
        const uint32_t sKb2 = sK + buf * KVBUF_B;
        const uint32_t sVb2 = sV + buf * KVBUF_B;

        float S[8][4];
#pragma unroll
        for (int j = 0; j < 8; j++)
#pragma unroll
            for (int r = 0; r < 4; r++) S[j][r] = 0.f;
#pragma unroll
        for (int ks = 0; ks < 4; ks++) {
            uint32_t bk[4][4];
#pragma unroll
            for (int nt = 0; nt < 4; nt++)
                ldsm_x4(bk[nt][0], bk[nt][1], bk[nt][2], bk[nt][3],
                        sKb2 + (bKrow + nt * 16) * 144 + ks * 32 + bKb);
#pragma unroll
            for (int j = 0; j < 8; j++)
                mma_f16(S[j][0], S[j][1], S[j][2], S[j][3],
                        Qf[ks][0], Qf[ks][1], Qf[ks][2], Qf[ks][3],
                        bk[j >> 1][(j & 1) * 2], bk[j >> 1][(j & 1) * 2 + 1]);
        }

        if (t >= ntiles - 2) {
#pragma unroll
            for (int j = 0; j < 8; j++) {
                int col = t * KT + j * 8 + 2 * (lane & 3);
                if (col     > grow0)     S[j][0] = -1e30f;
                if (col + 1 > grow0)     S[j][1] = -1e30f;
                if (col     > grow0 + 8) S[j][2] = -1e30f;
                if (col + 1 > grow0 + 8) S[j][3] = -1e30f;
            }
        }

        float t0 = -1e30f, t1 = -1e30f;
#pragma unroll
        for (int j = 0; j < 8; j++) {
            t0 = fmaxf(t0, fmaxf(S[j][0], S[j][1]));
            t1 = fmaxf(t1, fmaxf(S[j][2], S[j][3]));
        }
        t0 = fmaxf(t0, __shfl_xor_sync(0xffffffffu, t0, 1));
        t0 = fmaxf(t0, __shfl_xor_sync(0xffffffffu, t0, 2));
        t1 = fmaxf(t1, __shfl_xor_sync(0xffffffffu, t1, 1));
        t1 = fmaxf(t1, __shfl_xor_sync(0xffffffffu, t1, 2));
        float nm0 = fmaxf(m0, t0), nm1 = fmaxf(m1, t1);
        float cr0 = __expf(m0 - nm0), cr1 = __expf(m1 - nm1);
        m0 = nm0; m1 = nm1;
        l0 *= cr0; l1 *= cr1;
#pragma unroll
        for (int j = 0; j < 8; j++) {
            O[j][0] *= cr0; O[j][1] *= cr0;
            O[j][2] *= cr1; O[j][3] *= cr1;
        }

        uint32_t Pa[8], Pb[8];
        float s0 = 0.f, s1 = 0.f;
#pragma unroll
        for (int j = 0; j < 8; j++) {
            float p0 = __expf(S[j][0] - m0), p1 = __expf(S[j][1] - m0);
            float p2 = __expf(S[j][2] - m1), p3 = __expf(S[j][3] - m1);
            s0 += p0 + p1; s1 += p2 + p3;
            __half2 ha = __floats2half2_rn(p0, p1);
            __half2 hb = __floats2half2_rn(p2, p3);
            Pa[j] = *(uint32_t*)&ha;
            Pb[j] = *(uint32_t*)&hb;
        }
        s0 += __shfl_xor_sync(0xffffffffu, s0, 1);
        s0 += __shfl_xor_sync(0xffffffffu, s0, 2);
        s1 += __shfl_xor_sync(0xffffffffu, s1, 1);
        s1 += __shfl_xor_sync(0xffffffffu, s1, 2);
        l0 += s0; l1 += s1;

#pragma unroll
        for (int ks = 0; ks < 4; ks++) {
#pragma unroll
            for (int np = 0; np < 4; np++) {
                uint32_t v0, v1, v2, v3;
                ldsm_x4t(v0, v1, v2, v3,
                         sVb2 + (ks * 16 + (vm & 1) * 8 + vr) * 144
                              + (np * 16 + (vm >> 1) * 8) * 2);
                mma_f16(O[2*np][0], O[2*np][1], O[2*np][2], O[2*np][3],
                        Pa[2*ks], Pb[2*ks], Pa[2*ks+1], Pb[2*ks+1], v0, v1);
                mma_f16(O[2*np+1][0], O[2*np+1][1], O[2*np+1][2], O[2*np+1][3],
                        Pa[2*ks], Pb[2*ks], Pa[2*ks+1], Pb[2*ks+1], v2, v3);
            }
        }

        __syncthreads();
        if (t + 2 < ntiles) {
            const size_t off = (size_t)(t + 2) * KT * 1024;
            uint32_t kd = sK + buf * KVBUF_B + lrow * 144;
            uint32_t vd = sV + buf * KVBUF_B + lrow * 144;
#pragma unroll
            for (int c = 0; c < 2; c++) {
                int ch = lch + c;
                cpa16(kd + ch * 16, kgK + off + ch * 8);
                cpa16(vd + ch * 16, kgV + off + ch * 8);
            }
        }
        cpa_commit();
    }

    const float i0 = 1.f / l0, i1 = 1.f / l1;
    __half* o0p = ATH + ((size_t)(b * SS + grow0)) * KDIM + h * DH + 2 * (lane & 3);
    __half* o1p = o0p + (size_t)8 * KDIM;
#pragma unroll
    for (int j = 0; j < 8; j++) {
        __half2 h01 = __floats2half2_rn(O[j][0] * i0, O[j][1] * i0);
        __half2 h23 = __floats2half2_rn(O[j][2] * i1, O[j][3] * i1);
        *(__half2*)(o0p + j * 8) = h01;
        *(__half2*)(o1p + j * 8) = h23;
    }
}

// ---------------------------------------------------------------- launch
extern "C" void kernel_launch(void* const* d_in, const int* in_sizes, int n_in,
                              void* d_out, int out_size)
{
    const float* hs = (const float*)d_in[0];
    const float* cs = (const float*)d_in[1];
    const float* sn = (const float*)d_in[2];
    const float* Wq = (const float*)d_in[4];
    const float* Wk = (const float*)d_in[5];
    const float* Wv = (const float*)d_in[6];
    const float* Wo = (const float*)d_in[7];
    float* out = (float*)d_out;

    float* qkv;
    cudaGetSymbolAddress((void**)&qkv, g_qkv);
    __half *hsh, *wh, *woh, *ath, *kv16;
    cudaGetSymbolAddress((void**)&hsh,  g_hs_h);
    cudaGetSymbolAddress((void**)&wh,   g_w_h);
    cudaGetSymbolAddress((void**)&woh,  g_wo_h);
    cudaGetSymbolAddress((void**)&ath,  g_at_h);
    cudaGetSymbolAddress((void**)&kv16, g_kv16);

    cudaFuncSetAttribute(gemm_f16, cudaFuncAttributeMaxDynamicSharedMemorySize, GSMEM);
    cudaFuncSetAttribute(attn_hmma, cudaFuncAttributeMaxDynamicSharedMemorySize, ASMEM);

    const int nHS = MROWS * KDIM;
    const int nW  = (QKVDIM + HIDD) * KDIM;
    conv_kernel<<<(nHS + 255) / 256, 256>>>(hs, hsh, nHS);
    conv_w_kernel<<<(nW + 255) / 256, 256>>>(Wq, Wk, Wv, Wo, wh, woh);

    // merged QKV projection
    gemm_f16<<<dim3(QKVDIM / 128, MROWS / 128), 256, GSMEM>>>(hsh, wh, qkv, QKVDIM);

    // fused K-RoPE + KV fp16 convert
    ropeKV_kernel<<<(MROWS * 512) / 256, 256>>>(qkv, cs, sn, kv16);

    // HMMA flash attention (Q-RoPE fused), QT=128
    attn_hmma<<<dim3(SS / QT, BB * NH), dim3(256), ASMEM>>>(qkv, kv16, cs, sn, ath);

    // output projection
    gemm_f16<<<dim3(HIDD / 128, MROWS / 128), 256, GSMEM>>>(ath, woh, out, HIDD);
}

// round 17
// speedup vs baseline: 1.2548x; 1.2548x over previous
#include <cuda_runtime.h>
#include <cuda_fp16.h>
#include <cstdint>
#include <math.h>

// ---------------------------------------------------------------- constants
#define BB   2
#define SS   2048
#define HIDD 2048
#define NH   32
#define NKV  8
#define DH   64
#define MROWS (BB*SS)        // 4096
#define KVDIM (NKV*DH)       // 512
#define KDIM  2048
#define QKVDIM (HIDD + 2*KVDIM)   // 3072

// ---------------------------------------------------------------- scratch
__device__ float  g_qkv [(size_t)MROWS * QKVDIM];   // 48 MB
__device__ __half g_hs_h[(size_t)MROWS * KDIM];     // 16 MB fp16(hs)
__device__ __half g_w_h [(size_t)QKVDIM * KDIM];    // 12 MB fp16(W) merged
__device__ __half g_wo_h[(size_t)HIDD  * KDIM];     //  8 MB
__device__ __half g_at_h[(size_t)MROWS * KDIM];     // 16 MB fp16(attn out)
__device__ __half g_kv16[(size_t)MROWS * 1024];     //  8 MB fp16 K|V (roped)

// ---------------------------------------------------------------- helpers
__device__ __forceinline__ uint32_t smem_u32(const void* p) {
    uint32_t a;
    asm("{ .reg .u64 t; cvta.to.shared.u64 t, %1; cvt.u32.u64 %0, t; }" : "=r"(a) : "l"(p));
    return a;
}
__device__ __forceinline__ void cpa16(uint32_t s, const void* g) {
    asm volatile("cp.async.cg.shared.global [%0], [%1], 16;" :: "r"(s), "l"(g));
}
__device__ __forceinline__ void cpa_commit() {
    asm volatile("cp.async.commit_group;" ::: "memory");
}
template<int N> __device__ __forceinline__ void cpa_wait() {
    asm volatile("cp.async.wait_group %0;" :: "n"(N) : "memory");
}
__device__ __forceinline__ void ldsm_x4(uint32_t& r0, uint32_t& r1, uint32_t& r2, uint32_t& r3,
                                        uint32_t addr) {
    asm volatile("ldmatrix.sync.aligned.m8n8.x4.shared.b16 {%0,%1,%2,%3}, [%4];"
                 : "=r"(r0), "=r"(r1), "=r"(r2), "=r"(r3) : "r"(addr));
}
__device__ __forceinline__ void ldsm_x4t(uint32_t& r0, uint32_t& r1, uint32_t& r2, uint32_t& r3,
                                         uint32_t addr) {
    asm volatile("ldmatrix.sync.aligned.m8n8.x4.trans.shared.b16 {%0,%1,%2,%3}, [%4];"
                 : "=r"(r0), "=r"(r1), "=r"(r2), "=r"(r3) : "r"(addr));
}
__device__ __forceinline__ void mma_f16(float& c0, float& c1, float& c2, float& c3,
                                        uint32_t a0, uint32_t a1, uint32_t a2, uint32_t a3,
                                        uint32_t b0, uint32_t b1) {
    asm volatile(
        "mma.sync.aligned.m16n8k16.row.col.f32.f16.f16.f32 "
        "{%0,%1,%2,%3}, {%4,%5,%6,%7}, {%8,%9}, {%0,%1,%2,%3};"
        : "+f"(c0), "+f"(c1), "+f"(c2), "+f"(c3)
        : "r"(a0), "r"(a1), "r"(a2), "r"(a3), "r"(b0), "r"(b1));
}
__device__ __forceinline__ uint2 cvt4(float4 v) {
    __half2 lo = __floats2half2_rn(v.x, v.y);
    __half2 hi = __floats2half2_rn(v.z, v.w);
    return make_uint2(*(uint32_t*)&lo, *(uint32_t*)&hi);
}

// ---------------------------------------------------------------- converts (vectorized x4)
__global__ void conv_kernel(const float* __restrict__ s, __half* __restrict__ d, int n4) {
    int idx = blockIdx.x * blockDim.x + threadIdx.x;
    if (idx < n4)
        *(uint2*)(d + idx * 4) = cvt4(*(const float4*)(s + idx * 4));
}
__global__ void conv_w_kernel(const float* __restrict__ Wq, const float* __restrict__ Wk,
                              const float* __restrict__ Wv, const float* __restrict__ Wo,
                              __half* __restrict__ wh, __half* __restrict__ woh) {
    int idx = blockIdx.x * blockDim.x + threadIdx.x;   // 4 elems per thread
    if (idx >= (QKVDIM + HIDD) * (KDIM / 4)) return;
    int e = idx * 4;
    int r = e >> 11;
    int k = e & (KDIM - 1);
    float4 x;
    if (r < HIDD)                 x = *(const float4*)(Wq + (size_t)r * KDIM + k);
    else if (r < HIDD + KVDIM)    x = *(const float4*)(Wk + (size_t)(r - HIDD) * KDIM + k);
    else if (r < QKVDIM)          x = *(const float4*)(Wv + (size_t)(r - HIDD - KVDIM) * KDIM + k);
    else                          x = *(const float4*)(Wo + (size_t)(r - QKVDIM) * KDIM + k);
    if (r < QKVDIM) *(uint2*)(wh + e) = cvt4(x);
    else            *(uint2*)(woh + (size_t)(r - QKVDIM) * KDIM + k) = cvt4(x);
}
// Fused: rope K (fp32 read from qkv) -> fp16 kv buffer; convert V -> fp16.
__global__ void ropeKV_kernel(const float* __restrict__ qkv,
                              const float* __restrict__ cs, const float* __restrict__ sn,
                              __half* __restrict__ kv) {
    int idx = blockIdx.x * blockDim.x + threadIdx.x;
    const int KP = MROWS * 256;
    if (idx < KP) {
        int d = idx & 31;
        int h = (idx >> 5) & (NKV - 1);
        int r = idx >> 8;
        float c = cs[r * DH + d], s = sn[r * DH + d];
        const float* p = qkv + (size_t)r * QKVDIM + HIDD + h * DH + d;
        float x1 = p[0], x2 = p[32];
        kv[(size_t)r * 1024 + h * DH + d]      = __float2half(x1 * c - x2 * s);
        kv[(size_t)r * 1024 + h * DH + d + 32] = __float2half(x2 * c + x1 * s);
    } else {
        int e = idx - KP;
        int r = e >> 7;                               // 128 threads per row, 4 elems each
        int c4 = (e & 127) * 4;
        const float* p = qkv + (size_t)r * QKVDIM + HIDD + 512 + c4;
        *(uint2*)(kv + (size_t)r * 1024 + 512 + c4) = cvt4(*(const float4*)p);
    }
}

// ---------------------------------------------------------------- fp16 HMMA GEMM (R15 exact)
#define BK3   32
#define NKIT  (KDIM / BK3)       // 64
#define SROWB 80
#define ATILE_B (128 * SROWB)
#define STAGE_B (2 * ATILE_B)
#define GSMEM  (3 * STAGE_B)

__global__ __launch_bounds__(256, 2) void gemm_f16(
    const __half* __restrict__ A, const __half* __restrict__ B,
    float* __restrict__ C, int N)
{
    extern __shared__ __align__(128) char smem[];
    const uint32_t sb = smem_u32(smem);
    const int tid  = threadIdx.x;
    const int lane = tid & 31;
    const int wid  = tid >> 5;
    const int wm   = wid & 3;
    const int wn   = wid >> 2;
    const int bm = blockIdx.y * 128, bn = blockIdx.x * 128;

    const int lrow = tid >> 1;
    const int lc   = (tid & 1) * 2;
    const __half* Ab = A + (size_t)(bm + lrow) * KDIM + lc * 8;
    const __half* Bb = B + (size_t)(bn + lrow) * KDIM + lc * 8;
    const uint32_t saA = sb + lrow * SROWB + lc * 16;
    const uint32_t saB = sb + ATILE_B + lrow * SROWB + lc * 16;

    float acc[2][8][4];
#pragma unroll
    for (int i = 0; i < 2; i++)
#pragma unroll
        for (int j = 0; j < 8; j++)
#pragma unroll
            for (int r = 0; r < 4; r++) acc[i][j][r] = 0.f;

    const int a_row = wm * 32 + (lane & 15);
    const int a_kb  = (lane >> 4) * 16;
    const int b_row = wn * 64 + ((lane >> 4) << 3) + (lane & 7);
    const int b_kb  = ((lane >> 3) & 1) * 16;

#pragma unroll
    for (int s = 0; s < 2; s++) {
        cpa16(saA + s * STAGE_B,      Ab + s * BK3);
        cpa16(saA + s * STAGE_B + 16, Ab + s * BK3 + 8);
        cpa16(saB + s * STAGE_B,      Bb + s * BK3);
        cpa16(saB + s * STAGE_B + 16, Bb + s * BK3 + 8);
        cpa_commit();
    }

    for (int kt = 0; kt < NKIT; kt++) {
        cpa_wait<1>();
        __syncthreads();

        if (kt + 2 < NKIT) {
            const int ps = (kt + 2) % 3;
            const int k0 = (kt + 2) * BK3;
            cpa16(saA + ps * STAGE_B,      Ab + k0);
            cpa16(saA + ps * STAGE_B + 16, Ab + k0 + 8);
            cpa16(saB + ps * STAGE_B,      Bb + k0);
            cpa16(saB + ps * STAGE_B + 16, Bb + k0 + 8);
        }
        cpa_commit();

        const uint32_t sAs = sb + (kt % 3) * STAGE_B;
        const uint32_t sBs = sAs + ATILE_B;

#pragma unroll
        for (int kh = 0; kh < 2; kh++) {
            const int kbyte = kh * 32;
            uint32_t a[2][4];
#pragma unroll
            for (int mt = 0; mt < 2; mt++)
                ldsm_x4(a[mt][0], a[mt][1], a[mt][2], a[mt][3],
                        sAs + (a_row + mt * 16) * SROWB + kbyte + a_kb);
            uint32_t b[4][4];
#pragma unroll
            for (int nt = 0; nt < 4; nt++)
                ldsm_x4(b[nt][0], b[nt][1], b[nt][2], b[nt][3],
                        sBs + (b_row + nt * 16) * SROWB + kbyte + b_kb);
#pragma unroll
            for (int mt = 0; mt < 2; mt++)
#pragma unroll
                for (int j = 0; j < 8; j++)
                    mma_f16(acc[mt][j][0], acc[mt][j][1], acc[mt][j][2], acc[mt][j][3],
                            a[mt][0], a[mt][1], a[mt][2], a[mt][3],
                            b[j >> 1][(j & 1) * 2], b[j >> 1][(j & 1) * 2 + 1]);
        }
        __syncthreads();
    }

#pragma unroll
    for (int mt = 0; mt < 2; mt++) {
        int m0 = bm + wm * 32 + mt * 16 + (lane >> 2);
#pragma unroll
        for (int j = 0; j < 8; j++) {
            int n0 = bn + wn * 64 + j * 8 + (lane & 3) * 2;
            float2 v0 = { acc[mt][j][0], acc[mt][j][1] };
            float2 v1 = { acc[mt][j][2], acc[mt][j][3] };
            *(float2*)(C + (size_t)m0 * N + n0)       = v0;
            *(float2*)(C + (size_t)(m0 + 8) * N + n0) = v1;
        }
    }
}

// ---------------------------------------------------------------- HMMA flash attention (R15 exact)
#define QT 128
#define KT 64
#define PADH 72                       // halves per smem row (144 B)
#define QBUF_B (QT * PADH * 2)        // 18432 B
#define KVBUF_B (KT * PADH * 2)       // 9216 B per buffer
#define ASMEM (QBUF_B + 4 * KVBUF_B)  // 55296 B

__global__ __launch_bounds__(256) void attn_hmma(
    const float* __restrict__ QKV, const __half* __restrict__ KV,
    const float* __restrict__ cs, const float* __restrict__ sn,
    __half* __restrict__ ATH)
{
    extern __shared__ __align__(16) char asmem[];
    const uint32_t sQ = smem_u32(asmem);
    const uint32_t sK = sQ + QBUF_B;
    const uint32_t sV = sK + 2 * KVBUF_B;

    const int tid  = threadIdx.x;
    const int lane = tid & 31;
    const int w    = tid >> 5;
    const int b    = blockIdx.y >> 5;
    const int h    = blockIdx.y & 31;
    const int kvh  = h >> 2;
    const int qt   = gridDim.x - 1 - blockIdx.x;
    const int qbase = qt * QT;
    const int ntiles = 2 * (qt + 1);

    const int lrow = tid >> 2;
    const int lch  = (tid & 3) * 2;
    const __half* kgK = KV + ((size_t)(b * SS) + lrow) * 1024 + kvh * DH;
    const __half* kgV = kgK + 512;
#pragma unroll
    for (int p = 0; p < 2; p++) {
        {
            const size_t off = (size_t)p * KT * 1024;
            uint32_t kd = sK + p * KVBUF_B + lrow * 144;
            uint32_t vd = sV + p * KVBUF_B + lrow * 144;
#pragma unroll
            for (int c = 0; c < 2; c++) {
                int ch = lch + c;
                cpa16(kd + ch * 16, kgK + off + ch * 8);
                cpa16(vd + ch * 16, kgV + off + ch * 8);
            }
        }
        cpa_commit();
    }

    // Q load + RoPE + scale -> fp16 smem
    {
        const int row = tid >> 1;
        const int hs  = tid & 1;
        const int grow = qbase + row;
        const float* qp = QKV + ((size_t)(b * SS + grow)) * QKVDIM + h * DH;
        const float* cp = cs + (size_t)(b * SS + grow) * DH;
        const float* sp = sn + (size_t)(b * SS + grow) * DH;
        __half* qrow = (__half*)(asmem) + row * PADH;
#pragma unroll
        for (int i = 0; i < 8; i++) {
            int d0 = hs * 32 + i * 4;
            float4 xv = *(const float4*)(qp + d0);
            float4 pv = *(const float4*)(qp + (d0 ^ 32));
            float4 cv = *(const float4*)(cp + d0);
            float4 sv = *(const float4*)(sp + d0);
            float o0, o1, o2, o3;
            if (hs == 0) {
                o0 = (xv.x*cv.x - pv.x*sv.x)*0.125f; o1 = (xv.y*cv.y - pv.y*sv.y)*0.125f;
                o2 = (xv.z*cv.z - pv.z*sv.z)*0.125f; o3 = (xv.w*cv.w - pv.w*sv.w)*0.125f;
            } else {
                o0 = (xv.x*cv.x + pv.x*sv.x)*0.125f; o1 = (xv.y*cv.y + pv.y*sv.y)*0.125f;
                o2 = (xv.z*cv.z + pv.z*sv.z)*0.125f; o3 = (xv.w*cv.w + pv.w*sv.w)*0.125f;
            }
            *(__half2*)(qrow + d0)     = __floats2half2_rn(o0, o1);
            *(__half2*)(qrow + d0 + 2) = __floats2half2_rn(o2, o3);
        }
    }
    __syncthreads();

    uint32_t Qf[4][4];
    {
        const int a_row = w * 16 + (lane & 15);
        const int a_kb  = (lane >> 4) * 16;
#pragma unroll
        for (int ks = 0; ks < 4; ks++)
            ldsm_x4(Qf[ks][0], Qf[ks][1], Qf[ks][2], Qf[ks][3],
                    sQ + a_row * 144 + ks * 32 + a_kb);
    }

    float O[8][4];
#pragma unroll
    for (int j = 0; j < 8; j++)
#pragma unroll
        for (int r = 0; r < 4; r++) O[j][r] = 0.f;
    float m0 = -1e30f, m1 = -1e30f, l0 = 0.f, l1 = 0.f;

    const int bKrow = ((lane >> 4) << 3) + (lane & 7);
    const int bKb   = ((lane >> 3) & 1) * 16;
    const int vm = lane >> 3, vr = lane & 7;
    const int grow0 = qbase + w * 16 + (lane >> 2);

    for (int t = 0; t < ntiles; t++) {
        cpa_wait<1>();
        __syncthreads();
        const int buf = t & 1;
        const uint32_t sKb2 = sK + buf * KVBUF_B;
        const uint32_t sVb2 = sV + buf * KVBUF_B;

        float S[8][4];
#pragma unroll
        for (int j = 0; j < 8; j++)
#pragma unroll
            for (int r = 0; r < 4; r++) S[j][r] = 0.f;
#pragma unroll
        for (int ks = 0; ks < 4; ks++) {
            uint32_t bk[4][4];
#pragma unroll
            for (int nt = 0; nt < 4; nt++)
                ldsm_x4(bk[nt][0], bk[nt][1], bk[nt][2], bk[nt][3],
                        sKb2 + (bKrow + nt * 16) * 144 + ks * 32 + bKb);
#pragma unroll
            for (int j = 0; j < 8; j++)
                mma_f16(S[j][0], S[j][1], S[j][2], S[j][3],
                        Qf[ks][0], Qf[ks][1], Qf[ks][2], Qf[ks][3],
                        bk[j >> 1][(j & 1) * 2], bk[j >> 1][(j & 1) * 2 + 1]);
        }

        if (t >= ntiles - 2) {
#pragma unroll
            for (int j = 0; j < 8; j++) {
                int col = t * KT + j * 8 + 2 * (lane & 3);
                if (col     > grow0)     S[j][0] = -1e30f;
                if (col + 1 > grow0)     S[j][1] = -1e30f;
                if (col     > grow0 + 8) S[j][2] = -1e30f;
                if (col + 1 > grow0 + 8) S[j][3] = -1e30f;
            }
        }

        float t0 = -1e30f, t1 = -1e30f;
#pragma unroll
        for (int j = 0; j < 8; j++) {
            t0 = fmaxf(t0, fmaxf(S[j][0], S[j][1]));
            t1 = fmaxf(t1, fmaxf(S[j][2], S[j][3]));
        }
        t0 = fmaxf(t0, __shfl_xor_sync(0xffffffffu, t0, 1));
        t0 = fmaxf(t0, __shfl_xor_sync(0xffffffffu, t0, 2));
        t1 = fmaxf(t1, __shfl_xor_sync(0xffffffffu, t1, 1));
        t1 = fmaxf(t1, __shfl_xor_sync(0xffffffffu, t1, 2));
        float nm0 = fmaxf(m0, t0), nm1 = fmaxf(m1, t1);
        float cr0 = __expf(m0 - nm0), cr1 = __expf(m1 - nm1);
        m0 = nm0; m1 = nm1;
        l0 *= cr0; l1 *= cr1;
#pragma unroll
        for (int j = 0; j < 8; j++) {
            O[j][0] *= cr0; O[j][1] *= cr0;
            O[j][2] *= cr1; O[j][3] *= cr1;
        }

        uint32_t Pa[8], Pb[8];
        float s0 = 0.f, s1 = 0.f;
#pragma unroll
        for (int j = 0; j < 8; j++) {
            float p0 = __expf(S[j][0] - m0), p1 = __expf(S[j][1] - m0);
            float p2 = __expf(S[j][2] - m1), p3 = __expf(S[j][3] - m1);
            s0 += p0 + p1; s1 += p2 + p3;
            __half2 ha = __floats2half2_rn(p0, p1);
            __half2 hb = __floats2half2_rn(p2, p3);
            Pa[j] = *(uint32_t*)&ha;
            Pb[j] = *(uint32_t*)&hb;
        }
        s0 += __shfl_xor_sync(0xffffffffu, s0, 1);
        s0 += __shfl_xor_sync(0xffffffffu, s0, 2);
        s1 += __shfl_xor_sync(0xffffffffu, s1, 1);
        s1 += __shfl_xor_sync(0xffffffffu, s1, 2);
        l0 += s0; l1 += s1;

#pragma unroll
        for (int ks = 0; ks < 4; ks++) {
#pragma unroll
            for (int np = 0; np < 4; np++) {
                uint32_t v0, v1, v2, v3;
                ldsm_x4t(v0, v1, v2, v3,
                         sVb2 + (ks * 16 + (vm & 1) * 8 + vr) * 144
                              + (np * 16 + (vm >> 1) * 8) * 2);
                mma_f16(O[2*np][0], O[2*np][1], O[2*np][2], O[2*np][3],
                        Pa[2*ks], Pb[2*ks], Pa[2*ks+1], Pb[2*ks+1], v0, v1);
                mma_f16(O[2*np+1][0], O[2*np+1][1], O[2*np+1][2], O[2*np+1][3],
                        Pa[2*ks], Pb[2*ks], Pa[2*ks+1], Pb[2*ks+1], v2, v3);
            }
        }

        __syncthreads();
        if (t + 2 < ntiles) {
            const size_t off = (size_t)(t + 2) * KT * 1024;
            uint32_t kd = sK + buf * KVBUF_B + lrow * 144;
            uint32_t vd = sV + buf * KVBUF_B + lrow * 144;
#pragma unroll
            for (int c = 0; c < 2; c++) {
                int ch = lch + c;
                cpa16(kd + ch * 16, kgK + off + ch * 8);
                cpa16(vd + ch * 16, kgV + off + ch * 8);
            }
        }
        cpa_commit();
    }

    const float i0 = 1.f / l0, i1 = 1.f / l1;
    __half* o0p = ATH + ((size_t)(b * SS + grow0)) * KDIM + h * DH + 2 * (lane & 3);
    __half* o1p = o0p + (size_t)8 * KDIM;
#pragma unroll
    for (int j = 0; j < 8; j++) {
        __half2 h01 = __floats2half2_rn(O[j][0] * i0, O[j][1] * i0);
        __half2 h23 = __floats2half2_rn(O[j][2] * i1, O[j][3] * i1);
        *(__half2*)(o0p + j * 8) = h01;
        *(__half2*)(o1p + j * 8) = h23;
    }
}

// ---------------------------------------------------------------- launch
extern "C" void kernel_launch(void* const* d_in, const int* in_sizes, int n_in,
                              void* d_out, int out_size)
{
    const float* hs = (const float*)d_in[0];
    const float* cs = (const float*)d_in[1];
    const float* sn = (const float*)d_in[2];
    const float* Wq = (const float*)d_in[4];
    const float* Wk = (const float*)d_in[5];
    const float* Wv = (const float*)d_in[6];
    const float* Wo = (const float*)d_in[7];
    float* out = (float*)d_out;

    float* qkv;
    cudaGetSymbolAddress((void**)&qkv, g_qkv);
    __half *hsh, *wh, *woh, *ath, *kv16;
    cudaGetSymbolAddress((void**)&hsh,  g_hs_h);
    cudaGetSymbolAddress((void**)&wh,   g_w_h);
    cudaGetSymbolAddress((void**)&woh,  g_wo_h);
    cudaGetSymbolAddress((void**)&ath,  g_at_h);
    cudaGetSymbolAddress((void**)&kv16, g_kv16);

    cudaFuncSetAttribute(gemm_f16, cudaFuncAttributeMaxDynamicSharedMemorySize, GSMEM);
    cudaFuncSetAttribute(attn_hmma, cudaFuncAttributeMaxDynamicSharedMemorySize, ASMEM);

    const int nHS4 = MROWS * KDIM / 4;
    const int nW4  = (QKVDIM + HIDD) * (KDIM / 4);
    conv_kernel<<<(nHS4 + 255) / 256, 256>>>(hs, hsh, nHS4);
    conv_w_kernel<<<(nW4 + 255) / 256, 256>>>(Wq, Wk, Wv, Wo, wh, woh);

    // merged QKV projection
    gemm_f16<<<dim3(QKVDIM / 128, MROWS / 128), 256, GSMEM>>>(hsh, wh, qkv, QKVDIM);

    // fused K-RoPE + KV fp16 convert (V path vectorized x4)
    ropeKV_kernel<<<(MROWS * 256 + MROWS * 128) / 256, 256>>>(qkv, cs, sn, kv16);

    // HMMA flash attention (Q-RoPE fused), QT=128
    attn_hmma<<<dim3(SS / QT, BB * NH), dim3(256), ASMEM>>>(qkv, kv16, cs, sn, ath);

    // output projection
    gemm_f16<<<dim3(HIDD / 128, MROWS / 128), 256, GSMEM>>>(ath, woh, out, HIDD);
}